// round 14
// baseline (speedup 1.0000x reference)
#include <cuda_runtime.h>
#include <cstdint>
#include <cstddef>

// ---------------- constants ----------------
static constexpr int BM = 128;                 // M rows per CTA
static constexpr int BN = 128;                 // N cols per CTA
static constexpr int NCHUNK = 9;               // K = 576 (568 + pad) in chunks of 64
static constexpr int MTOT = 262144;
static constexpr int GRID_M = MTOT / BM;       // 2048
static constexpr int NTHR = 256;

// dynamic smem
static constexpr uint32_t A_STAGE_SZ = 16384;             // fp16 A image (128 x 128B)
static constexpr uint32_t B_BASE     = 32768;
static constexpr uint32_t B_STAGE_SZ = 16384;             // fp16 B image (128 x 128B)
static constexpr uint32_t OFF_BIAS   = B_BASE + 2 * B_STAGE_SZ;   // 65536
static constexpr uint32_t OFF_BAR    = OFF_BIAS + 512;            // 2 mbarriers
static constexpr uint32_t OFF_ARAW   = OFF_BAR + 128;             // 66176
static constexpr uint32_t SMEM_TOTAL = OFF_ARAW + 32768;          // 98944

// prepacked swizzled B image (fp16): [chunk][n=0..255][k=0..63]  -> 32KB per chunk
__device__ __align__(128) uint32_t g_Bh[NCHUNK * 8192];

// compaction state (two-sided: actives from front, inactives from back)
__device__ int g_idx[MTOT];
__device__ int g_blockcnt[64];
__device__ int g_NA;

// ---------------- helpers ----------------
__device__ __forceinline__ uint32_t smem_u32(const void* p) {
    uint32_t a;
    asm("{ .reg .u64 t; cvta.to.shared.u64 t, %1; cvt.u32.u64 %0, t; }"
        : "=r"(a) : "l"(p));
    return a;
}
__device__ __forceinline__ uint32_t f2h2(float lo, float hi) {
    uint32_t r;
    asm("cvt.rn.f16x2.f32 %0, %1, %2;" : "=r"(r) : "f"(hi), "f"(lo));
    return r;
}
#define SW128(o) ((o) ^ (((o) >> 3) & 0x70))

__device__ __forceinline__ void mbar_init(uint32_t a, uint32_t cnt) {
    asm volatile("mbarrier.init.shared.b64 [%0], %1;" :: "r"(a), "r"(cnt) : "memory");
}
__device__ __forceinline__ void mbar_expect(uint32_t a, uint32_t bytes) {
    asm volatile("mbarrier.arrive.expect_tx.shared.b64 _, [%0], %1;"
                 :: "r"(a), "r"(bytes) : "memory");
}
__device__ __forceinline__ void mbar_wait(uint32_t a, uint32_t ph) {
    asm volatile(
        "{\n\t.reg .pred P;\n"
        "WL%=:\n\t"
        "mbarrier.try_wait.parity.acquire.cta.shared::cta.b64 P, [%0], %1, 0x989680;\n\t"
        "@P bra WD%=;\n\t"
        "bra WL%=;\n"
        "WD%=:\n\t}"
        :: "r"(a), "r"(ph) : "memory");
}
__device__ __forceinline__ void bulk_g2s(uint32_t dst, const void* src,
                                         uint32_t bytes, uint32_t mbar) {
    asm volatile(
        "cp.async.bulk.shared::cta.global.mbarrier::complete_tx::bytes [%0], [%1], %2, [%3];"
        :: "r"(dst), "l"(src), "r"(bytes), "r"(mbar) : "memory");
}
__device__ __forceinline__ void cp16(uint32_t dst, const void* src) {
    asm volatile("cp.async.cg.shared.global [%0], [%1], 16;"
                 :: "r"(dst), "l"(src) : "memory");
}
__device__ __forceinline__ void cp_commit() {
    asm volatile("cp.async.commit_group;" ::: "memory");
}
template <int N>
__device__ __forceinline__ void cp_wait() {
    asm volatile("cp.async.wait_group %0;" :: "n"(N) : "memory");
}
__device__ __forceinline__ void ldsm4(uint32_t* r, uint32_t a) {
    asm volatile("ldmatrix.sync.aligned.m8n8.x4.shared.b16 {%0,%1,%2,%3}, [%4];"
                 : "=r"(r[0]), "=r"(r[1]), "=r"(r[2]), "=r"(r[3]) : "r"(a));
}
__device__ __forceinline__ void mma16816(float& d0, float& d1, float& d2, float& d3,
                                         const uint32_t* a, uint32_t b0, uint32_t b1) {
    asm volatile(
        "mma.sync.aligned.m16n8k16.row.col.f32.f16.f16.f32 "
        "{%0,%1,%2,%3}, {%4,%5,%6,%7}, {%8,%9}, {%0,%1,%2,%3};"
        : "+f"(d0), "+f"(d1), "+f"(d2), "+f"(d3)
        : "r"(a[0]), "r"(a[1]), "r"(a[2]), "r"(a[3]), "r"(b0), "r"(b1));
}

// ---------------- prep1: mask count (blocks 0..63) + pack W (blocks 64..99) ----------------
__device__ __forceinline__ float fetchW(int k, int n, const float* appW,
                                        const float* stW) {
    if (k <= 512) return appW[(size_t)k * 256 + n];
    if (k < 568)  return stW[(size_t)(k - 513) * 256 + n];
    return 0.0f;
}

__global__ void k_prep1(const float* __restrict__ appW,
                        const float* __restrict__ stW,
                        const int* __restrict__ mask) {
    int t = threadIdx.x;
    if (blockIdx.x < 64) {
        int b = blockIdx.x;
        const int4* m4 = reinterpret_cast<const int4*>(mask) + (size_t)b * 1024 + t * 4;
        int cnt = 0;
#pragma unroll
        for (int i = 0; i < 4; i++) {
            int4 x = m4[i];
            cnt += (x.x != 0) + (x.y != 0) + (x.z != 0) + (x.w != 0);
        }
#pragma unroll
        for (int o = 16; o > 0; o >>= 1) cnt += __shfl_down_sync(0xFFFFFFFFu, cnt, o);
        __shared__ int ws[8];
        if ((t & 31) == 0) ws[t >> 5] = cnt;
        __syncthreads();
        if (t == 0) {
            int s = 0;
#pragma unroll
            for (int i = 0; i < 8; i++) s += ws[i];
            g_blockcnt[b] = s;
        }
    } else {
        int bb    = blockIdx.x - 64;     // 0..35
        int chunk = bb >> 2;             // 0..8
        int q     = bb & 3;              // 0..3 -> kp quarter
        int n = t;
#pragma unroll
        for (int kp = q * 8; kp < q * 8 + 8; kp++) {
            int k0 = chunk * 64 + kp * 2;
            uint32_t hw = f2h2(fetchW(k0, n, appW, stW), fetchW(k0 + 1, n, appW, stW));
            uint32_t off = SW128((uint32_t)(n * 128 + kp * 4));
            g_Bh[chunk * 8192 + (off >> 2)] = hw;
        }
    }
}

// ---------------- prep2: scan block counts + two-sided scatter (64 blocks) ----------------
__global__ void k_prep2(const int* __restrict__ mask) {
    __shared__ int sc[64];
    __shared__ int s[256];
    __shared__ int boff;
    int b = blockIdx.x, t = threadIdx.x;

    if (t < 64) sc[t] = g_blockcnt[t];
    __syncthreads();
    for (int d = 1; d < 64; d <<= 1) {
        int add = (t >= d && t < 64) ? sc[t - d] : 0;
        __syncthreads();
        if (t < 64) sc[t] += add;
        __syncthreads();
    }
    if (t == 0) {
        boff = (b == 0) ? 0 : sc[b - 1];
        if (b == 0) g_NA = sc[63];
    }
    __syncthreads();

    int r0 = b * 4096 + t * 16;
    const int4* m4 = reinterpret_cast<const int4*>(mask) + (size_t)b * 1024 + t * 4;
    int m[16], cnt = 0;
#pragma unroll
    for (int i = 0; i < 4; i++) {
        int4 x = m4[i];
        m[4 * i + 0] = (x.x != 0); m[4 * i + 1] = (x.y != 0);
        m[4 * i + 2] = (x.z != 0); m[4 * i + 3] = (x.w != 0);
        cnt += m[4 * i] + m[4 * i + 1] + m[4 * i + 2] + m[4 * i + 3];
    }
    s[t] = cnt;
    __syncthreads();
    for (int d = 1; d < 256; d <<= 1) {
        int add = (t >= d) ? s[t - d] : 0;
        __syncthreads();
        s[t] += add;
        __syncthreads();
    }
    int act_excl = boff + s[t] - cnt;
#pragma unroll
    for (int i = 0; i < 16; i++) {
        int r = r0 + i;
        if (m[i]) {
            g_idx[act_excl] = r;
            act_excl++;
        } else {
            int inact_excl = r - act_excl;
            g_idx[MTOT - 1 - inact_excl] = r;
        }
    }
}

// ---------------- main kernel ----------------
__global__ __launch_bounds__(NTHR, 2)
void seplin_mma(const float* __restrict__ emb,
                const float* __restrict__ vis,
                const float* __restrict__ bbox,
                const float* __restrict__ kpts,
                const float* __restrict__ appB,
                const float* __restrict__ stB,
                float* __restrict__ out) {
    const int na = g_NA;
    const int rowBase = blockIdx.y * BM;
    const int colBase = blockIdx.x * BN;
    const int tid  = threadIdx.x;

    // ---- pure-zero CTA: zero its 128x128 output block ----
    if (rowBase >= na) {
        int j   = tid >> 1;
        int seg = tid & 1;
        int realrow = g_idx[rowBase + j];
        float4* o4 = reinterpret_cast<float4*>(out + (size_t)realrow * 256 + colBase
                                               + seg * 64);
        float4 z = make_float4(0.f, 0.f, 0.f, 0.f);
#pragma unroll
        for (int i = 0; i < 16; i++) o4[i] = z;
        return;
    }

    extern __shared__ char smem[];
    const uint32_t sb = smem_u32(smem);
    const int lane = tid & 31;
    const int wid  = tid >> 5;
    const int warpM = wid >> 2;   // 0..1  (64 rows each)
    const int warpN = wid & 3;    // 0..3  (32 cols each)

    if (tid < 128)
        reinterpret_cast<float*>(smem + OFF_BIAS)[tid] =
            appB[colBase + tid] + stB[colBase + tid];
    if (tid == 0) {
        mbar_init(sb + OFF_BAR + 0, 1);
        mbar_init(sb + OFF_BAR + 8, 1);
    }
    asm volatile("fence.proxy.async.shared::cta;" ::: "memory");
    __syncthreads();

    // ldmatrix per-lane constants
    const uint32_t segBase = (uint32_t)(lane >> 4) * 16;
    uint32_t a_row128[4], a_xor[4];
#pragma unroll
    for (int mi = 0; mi < 4; mi++) {
        int r = warpM * 64 + mi * 16 + (lane & 15);
        a_row128[mi] = (uint32_t)r * 128;
        a_xor[mi]    = (uint32_t)(r & 7) << 4;
    }
    uint32_t b_row128[2], b_xor[2];
#pragma unroll
    for (int ng = 0; ng < 2; ng++) {
        int r = warpN * 32 + ng * 16 + (lane & 15);
        b_row128[ng] = (uint32_t)r * 128;
        b_xor[ng]    = (uint32_t)(r & 7) << 4;
    }

    // A mapping: 2 threads per row, 32 k each (128B)
    const int arow = tid >> 1;
    const int akb  = (tid & 1) * 32;
    const int asrc = g_idx[rowBase + arow];
    const uint32_t rawOff = (uint32_t)(arow * 256 + (tid & 1) * 128);

    float acc[4][4][4];
#pragma unroll
    for (int mi = 0; mi < 4; mi++)
#pragma unroll
        for (int ni = 0; ni < 4; ni++)
#pragma unroll
            for (int q = 0; q < 4; q++) acc[mi][ni][q] = 0.0f;

    auto loadB = [&](int c) {
        const uint32_t st  = B_BASE + (uint32_t)(c & 1) * B_STAGE_SZ;
        const uint32_t bar = sb + OFF_BAR + (uint32_t)(c & 1) * 8;
        mbar_expect(bar, 16384);
        bulk_g2s(sb + st,
                 reinterpret_cast<const char*>(g_Bh) + (size_t)c * 32768
                     + (size_t)colBase * 128,
                 16384, bar);
    };

    // async-fill raw fp32 A for chunk c (c<8); each thread fills its own 128B
    auto cpA = [&](int c) {
        const char* src = reinterpret_cast<const char*>(
            emb + (size_t)asrc * 512 + c * 64 + akb);
        uint32_t dst = sb + OFF_ARAW + rawOff;
#pragma unroll
        for (int i = 0; i < 8; i++) cp16(dst + i * 16, src + i * 16);
        cp_commit();
    };

    // convert own raw bytes -> swizzled fp16 image, stage (c&1)
    auto convA = [&](int c) {
        cp_wait<0>();
        const uint32_t ast = (uint32_t)(c & 1) * A_STAGE_SZ;
        float v[32];
        const float4* r4 = reinterpret_cast<const float4*>(smem + OFF_ARAW + rawOff);
#pragma unroll
        for (int q = 0; q < 8; q++) {
            float4 f = r4[q];
            v[4 * q + 0] = f.x; v[4 * q + 1] = f.y;
            v[4 * q + 2] = f.z; v[4 * q + 3] = f.w;
        }
        uint32_t hw[16];
#pragma unroll
        for (int p = 0; p < 16; p++) hw[p] = f2h2(v[2 * p], v[2 * p + 1]);
#pragma unroll
        for (int g = 0; g < 4; g++) {
            uint32_t off = SW128((uint32_t)(arow * 128 + (akb + 8 * g) * 2));
            *reinterpret_cast<uint4*>(smem + ast + off) =
                make_uint4(hw[4 * g], hw[4 * g + 1], hw[4 * g + 2], hw[4 * g + 3]);
        }
    };

    // chunk 8 (small-K gather) via LDG, stage 0
    auto prodA8 = [&]() {
        float v[32];
#pragma unroll
        for (int j = 0; j < 32; j++) {
            int i = akb + j;
            float val = 0.0f;
            if (i == 0)       val = vis[asrc];
            else if (i < 5)   val = bbox[(size_t)asrc * 4 + (i - 1)];
            else if (i < 56)  val = kpts[(size_t)asrc * 51 + (i - 5)];
            v[j] = val;
        }
        uint32_t hw[16];
#pragma unroll
        for (int p = 0; p < 16; p++) hw[p] = f2h2(v[2 * p], v[2 * p + 1]);
#pragma unroll
        for (int g = 0; g < 4; g++) {
            uint32_t off = SW128((uint32_t)(arow * 128 + (akb + 8 * g) * 2));
            *reinterpret_cast<uint4*>(smem + 0 + off) =       // stage 0 (8&1)
                make_uint4(hw[4 * g], hw[4 * g + 1], hw[4 * g + 2], hw[4 * g + 3]);
        }
    };

    // ---- prologue ----
    if (tid == 0) loadB(0);
    cpA(0);
    convA(0);                       // one-time exposed fill

    // ---- mainloop ----
    for (int c = 0; c < NCHUNK; c++) {
        const uint32_t baseA = sb + (uint32_t)(c & 1) * A_STAGE_SZ;
        const uint32_t baseB = sb + B_BASE + (uint32_t)(c & 1) * B_STAGE_SZ;

        __syncthreads();                     // A(c) visible; stage (c+1)&1 free
        if (tid == 0 && c + 1 < NCHUNK) loadB(c + 1);
        if (c + 1 < 8) cpA(c + 1);           // async raw fill for next chunk
        mbar_wait(sb + OFF_BAR + (uint32_t)(c & 1) * 8, (uint32_t)((c >> 1) & 1));

#pragma unroll
        for (int s = 0; s < 4; s++) {
            const uint32_t sseg = segBase + (uint32_t)s * 32;
            uint32_t bh[2][4];
#pragma unroll
            for (int ng = 0; ng < 2; ng++)
                ldsm4(bh[ng], baseB + b_row128[ng] + (sseg ^ b_xor[ng]));
#pragma unroll
            for (int mi = 0; mi < 4; mi++) {
                uint32_t ah[4];
                ldsm4(ah, baseA + a_row128[mi] + (sseg ^ a_xor[mi]));
#pragma unroll
                for (int ng = 0; ng < 2; ng++) {
                    float* d0 = acc[mi][2 * ng];
                    float* d1 = acc[mi][2 * ng + 1];
                    mma16816(d0[0], d0[1], d0[2], d0[3], ah, bh[ng][0], bh[ng][2]);
                    mma16816(d1[0], d1[1], d1[2], d1[3], ah, bh[ng][1], bh[ng][3]);
                }
            }
        }

        // produce A(c+1) fp16 image from the (completed) async raw fill
        if (c + 1 < 8)       convA(c + 1);
        else if (c + 1 == 8) prodA8();
    }

    // ---- epilogue: bias + permuted scatter store (zeros for inactive rows) ----
    const float* biasS = reinterpret_cast<const float*>(smem + OFF_BIAS);
    const int lr = lane >> 2;
    const int lc = (lane & 3) * 2;
#pragma unroll
    for (int mi = 0; mi < 4; mi++) {
#pragma unroll
        for (int dh = 0; dh < 2; dh++) {
            int rloc = warpM * 64 + mi * 16 + lr + dh * 8;
            int gr = rowBase + rloc;
            int realrow = g_idx[gr];
            float* orow = out + (size_t)realrow * 256 + colBase;
            if (gr < na) {
#pragma unroll
                for (int ni = 0; ni < 4; ni++) {
                    int cl = warpN * 32 + ni * 8 + lc;
                    float2 w;
                    w.x = acc[mi][ni][2 * dh + 0] + biasS[cl];
                    w.y = acc[mi][ni][2 * dh + 1] + biasS[cl + 1];
                    *reinterpret_cast<float2*>(orow + cl) = w;
                }
            } else {
#pragma unroll
                for (int ni = 0; ni < 4; ni++) {
                    int cl = warpN * 32 + ni * 8 + lc;
                    *reinterpret_cast<float2*>(orow + cl) = make_float2(0.f, 0.f);
                }
            }
        }
    }
}

// ---------------- launch ----------------
extern "C" void kernel_launch(void* const* d_in, const int* in_sizes, int n_in,
                              void* d_out, int out_size) {
    const float* emb  = (const float*)d_in[0];
    const float* vis  = (const float*)d_in[1];
    const float* bbox = (const float*)d_in[2];
    const float* kpts = (const float*)d_in[3];
    const int*   mask = (const int*)d_in[4];
    const float* appW = (const float*)d_in[5];
    const float* appB = (const float*)d_in[6];
    const float* stW  = (const float*)d_in[7];
    const float* stB  = (const float*)d_in[8];

    static int configured = 0;
    if (!configured) {
        cudaFuncSetAttribute(seplin_mma, cudaFuncAttributeMaxDynamicSharedMemorySize,
                             SMEM_TOTAL);
        configured = 1;
    }

    k_prep1<<<64 + 36, 256>>>(appW, stW, mask);
    k_prep2<<<64, 256>>>(mask);

    dim3 grid(256 / BN, GRID_M);   // (2, 2048)
    seplin_mma<<<grid, NTHR, SMEM_TOTAL>>>(emb, vis, bbox, kpts,
                                           appB, stB, (float*)d_out);
    (void)in_sizes; (void)n_in; (void)out_size;
}

// round 15
// speedup vs baseline: 1.3387x; 1.3387x over previous
#include <cuda_runtime.h>
#include <cstdint>
#include <cstddef>

// ---------------- constants ----------------
static constexpr int BM = 128;                 // M rows per CTA
static constexpr int BN = 128;                 // N cols per CTA
static constexpr int NCHUNK = 9;               // K = 576 (568 + pad) in chunks of 64
static constexpr int MTOT = 262144;
static constexpr int GRID_M = MTOT / BM;       // 2048
static constexpr int NTHR = 256;

// dynamic smem: A 2 stages x 16KB, B 2 stages x 16KB, bias, barriers
static constexpr uint32_t A_STAGE_SZ = 16384;             // fp16 A image (128 x 128B)
static constexpr uint32_t B_BASE     = 32768;
static constexpr uint32_t B_STAGE_SZ = 16384;             // fp16 B image (128 x 128B)
static constexpr uint32_t OFF_BIAS   = B_BASE + 2 * B_STAGE_SZ;   // 65536
static constexpr uint32_t OFF_BAR    = OFF_BIAS + 512;            // 2 mbarriers
static constexpr uint32_t SMEM_TOTAL = OFF_BAR + 64;              // 66112

// prepacked swizzled B image (fp16): [chunk][n=0..255][k=0..63]  -> 32KB per chunk
__device__ __align__(128) uint32_t g_Bh[NCHUNK * 8192];

// compaction state (two-sided: actives from front, inactives from back)
__device__ int g_idx[MTOT];
__device__ int g_blockcnt[64];
__device__ int g_NA;

// ---------------- helpers ----------------
__device__ __forceinline__ uint32_t smem_u32(const void* p) {
    uint32_t a;
    asm("{ .reg .u64 t; cvta.to.shared.u64 t, %1; cvt.u32.u64 %0, t; }"
        : "=r"(a) : "l"(p));
    return a;
}
__device__ __forceinline__ uint32_t f2h2(float lo, float hi) {
    uint32_t r;
    asm("cvt.rn.f16x2.f32 %0, %1, %2;" : "=r"(r) : "f"(hi), "f"(lo));
    return r;
}
#define SW128(o) ((o) ^ (((o) >> 3) & 0x70))

__device__ __forceinline__ void mbar_init(uint32_t a, uint32_t cnt) {
    asm volatile("mbarrier.init.shared.b64 [%0], %1;" :: "r"(a), "r"(cnt) : "memory");
}
__device__ __forceinline__ void mbar_expect(uint32_t a, uint32_t bytes) {
    asm volatile("mbarrier.arrive.expect_tx.shared.b64 _, [%0], %1;"
                 :: "r"(a), "r"(bytes) : "memory");
}
__device__ __forceinline__ void mbar_wait(uint32_t a, uint32_t ph) {
    asm volatile(
        "{\n\t.reg .pred P;\n"
        "WL%=:\n\t"
        "mbarrier.try_wait.parity.acquire.cta.shared::cta.b64 P, [%0], %1, 0x989680;\n\t"
        "@P bra WD%=;\n\t"
        "bra WL%=;\n"
        "WD%=:\n\t}"
        :: "r"(a), "r"(ph) : "memory");
}
__device__ __forceinline__ void bulk_g2s(uint32_t dst, const void* src,
                                         uint32_t bytes, uint32_t mbar) {
    asm volatile(
        "cp.async.bulk.shared::cta.global.mbarrier::complete_tx::bytes [%0], [%1], %2, [%3];"
        :: "r"(dst), "l"(src), "r"(bytes), "r"(mbar) : "memory");
}
__device__ __forceinline__ void ldsm4(uint32_t* r, uint32_t a) {
    asm volatile("ldmatrix.sync.aligned.m8n8.x4.shared.b16 {%0,%1,%2,%3}, [%4];"
                 : "=r"(r[0]), "=r"(r[1]), "=r"(r[2]), "=r"(r[3]) : "r"(a));
}
__device__ __forceinline__ void mma16816(float& d0, float& d1, float& d2, float& d3,
                                         const uint32_t* a, uint32_t b0, uint32_t b1) {
    asm volatile(
        "mma.sync.aligned.m16n8k16.row.col.f32.f16.f16.f32 "
        "{%0,%1,%2,%3}, {%4,%5,%6,%7}, {%8,%9}, {%0,%1,%2,%3};"
        : "+f"(d0), "+f"(d1), "+f"(d2), "+f"(d3)
        : "r"(a[0]), "r"(a[1]), "r"(a[2]), "r"(a[3]), "r"(b0), "r"(b1));
}

// ---------------- prep1: mask count (blocks 0..63) + pack W (blocks 64..99) ----------------
__device__ __forceinline__ float fetchW(int k, int n, const float* appW,
                                        const float* stW) {
    if (k <= 512) return appW[(size_t)k * 256 + n];
    if (k < 568)  return stW[(size_t)(k - 513) * 256 + n];
    return 0.0f;
}

__global__ void k_prep1(const float* __restrict__ appW,
                        const float* __restrict__ stW,
                        const int* __restrict__ mask) {
    int t = threadIdx.x;
    if (blockIdx.x < 64) {
        int b = blockIdx.x;
        const int4* m4 = reinterpret_cast<const int4*>(mask) + (size_t)b * 1024 + t * 4;
        int cnt = 0;
#pragma unroll
        for (int i = 0; i < 4; i++) {
            int4 x = m4[i];
            cnt += (x.x != 0) + (x.y != 0) + (x.z != 0) + (x.w != 0);
        }
#pragma unroll
        for (int o = 16; o > 0; o >>= 1) cnt += __shfl_down_sync(0xFFFFFFFFu, cnt, o);
        __shared__ int ws[8];
        if ((t & 31) == 0) ws[t >> 5] = cnt;
        __syncthreads();
        if (t == 0) {
            int s = 0;
#pragma unroll
            for (int i = 0; i < 8; i++) s += ws[i];
            g_blockcnt[b] = s;
        }
    } else {
        int bb    = blockIdx.x - 64;     // 0..35
        int chunk = bb >> 2;             // 0..8
        int q     = bb & 3;              // 0..3 -> kp quarter
        int n = t;
#pragma unroll
        for (int kp = q * 8; kp < q * 8 + 8; kp++) {
            int k0 = chunk * 64 + kp * 2;
            uint32_t hw = f2h2(fetchW(k0, n, appW, stW), fetchW(k0 + 1, n, appW, stW));
            uint32_t off = SW128((uint32_t)(n * 128 + kp * 4));
            g_Bh[chunk * 8192 + (off >> 2)] = hw;
        }
    }
}

// ---------------- prep2: scan block counts + two-sided scatter (64 blocks) ----------------
__global__ void k_prep2(const int* __restrict__ mask) {
    __shared__ int sc[64];
    __shared__ int s[256];
    __shared__ int boff;
    int b = blockIdx.x, t = threadIdx.x;

    if (t < 64) sc[t] = g_blockcnt[t];
    __syncthreads();
    for (int d = 1; d < 64; d <<= 1) {
        int add = (t >= d && t < 64) ? sc[t - d] : 0;
        __syncthreads();
        if (t < 64) sc[t] += add;
        __syncthreads();
    }
    if (t == 0) {
        boff = (b == 0) ? 0 : sc[b - 1];
        if (b == 0) g_NA = sc[63];
    }
    __syncthreads();

    int r0 = b * 4096 + t * 16;
    const int4* m4 = reinterpret_cast<const int4*>(mask) + (size_t)b * 1024 + t * 4;
    int m[16], cnt = 0;
#pragma unroll
    for (int i = 0; i < 4; i++) {
        int4 x = m4[i];
        m[4 * i + 0] = (x.x != 0); m[4 * i + 1] = (x.y != 0);
        m[4 * i + 2] = (x.z != 0); m[4 * i + 3] = (x.w != 0);
        cnt += m[4 * i] + m[4 * i + 1] + m[4 * i + 2] + m[4 * i + 3];
    }
    s[t] = cnt;
    __syncthreads();
    for (int d = 1; d < 256; d <<= 1) {
        int add = (t >= d) ? s[t - d] : 0;
        __syncthreads();
        s[t] += add;
        __syncthreads();
    }
    int act_excl = boff + s[t] - cnt;
#pragma unroll
    for (int i = 0; i < 16; i++) {
        int r = r0 + i;
        if (m[i]) {
            g_idx[act_excl] = r;
            act_excl++;
        } else {
            int inact_excl = r - act_excl;
            g_idx[MTOT - 1 - inact_excl] = r;
        }
    }
}

// ---------------- main kernel (R12 structure: LDG-tail A producer) ----------------
__global__ __launch_bounds__(NTHR, 2)
void seplin_mma(const float* __restrict__ emb,
                const float* __restrict__ vis,
                const float* __restrict__ bbox,
                const float* __restrict__ kpts,
                const float* __restrict__ appB,
                const float* __restrict__ stB,
                float* __restrict__ out) {
    const int na = g_NA;
    const int rowBase = blockIdx.y * BM;
    const int colBase = blockIdx.x * BN;
    const int tid  = threadIdx.x;

    // ---- pure-zero CTA: zero its 128x128 output block ----
    if (rowBase >= na) {
        int j   = tid >> 1;
        int seg = tid & 1;
        int realrow = g_idx[rowBase + j];
        float4* o4 = reinterpret_cast<float4*>(out + (size_t)realrow * 256 + colBase
                                               + seg * 64);
        float4 z = make_float4(0.f, 0.f, 0.f, 0.f);
#pragma unroll
        for (int i = 0; i < 16; i++) o4[i] = z;
        return;
    }

    extern __shared__ char smem[];
    const uint32_t sb = smem_u32(smem);
    const int lane = tid & 31;
    const int wid  = tid >> 5;
    const int warpM = wid >> 2;   // 0..1  (64 rows each)
    const int warpN = wid & 3;    // 0..3  (32 cols each)

    if (tid < 128)
        reinterpret_cast<float*>(smem + OFF_BIAS)[tid] =
            appB[colBase + tid] + stB[colBase + tid];
    if (tid == 0) {
        mbar_init(sb + OFF_BAR + 0, 1);
        mbar_init(sb + OFF_BAR + 8, 1);
    }
    asm volatile("fence.proxy.async.shared::cta;" ::: "memory");
    __syncthreads();

    // ldmatrix per-lane constants
    const uint32_t segBase = (uint32_t)(lane >> 4) * 16;
    uint32_t a_row128[4], a_xor[4];
#pragma unroll
    for (int mi = 0; mi < 4; mi++) {
        int r = warpM * 64 + mi * 16 + (lane & 15);
        a_row128[mi] = (uint32_t)r * 128;
        a_xor[mi]    = (uint32_t)(r & 7) << 4;
    }
    uint32_t b_row128[2], b_xor[2];
#pragma unroll
    for (int ng = 0; ng < 2; ng++) {
        int r = warpN * 32 + ng * 16 + (lane & 15);
        b_row128[ng] = (uint32_t)r * 128;
        b_xor[ng]    = (uint32_t)(r & 7) << 4;
    }

    // A mapping: 2 threads per row, 32 k each
    const int arow = tid >> 1;
    const int akb  = (tid & 1) * 32;
    const int asrc = g_idx[rowBase + arow];

    float acc[4][4][4];
#pragma unroll
    for (int mi = 0; mi < 4; mi++)
#pragma unroll
        for (int ni = 0; ni < 4; ni++)
#pragma unroll
            for (int q = 0; q < 4; q++) acc[mi][ni][q] = 0.0f;

    auto loadB = [&](int c) {
        const uint32_t st  = B_BASE + (uint32_t)(c & 1) * B_STAGE_SZ;
        const uint32_t bar = sb + OFF_BAR + (uint32_t)(c & 1) * 8;
        mbar_expect(bar, 16384);
        bulk_g2s(sb + st,
                 reinterpret_cast<const char*>(g_Bh) + (size_t)c * 32768
                     + (size_t)colBase * 128,
                 16384, bar);
    };

    // load A chunk c (fp32), convert, store swizzled fp16 into stage
    auto prodA = [&](int c) {
        const uint32_t ast = (uint32_t)(c & 1) * A_STAGE_SZ;
        float v[32];
        if (c < 8) {
            const float4* s4 = reinterpret_cast<const float4*>(
                emb + (size_t)asrc * 512 + c * 64 + akb);
#pragma unroll
            for (int q = 0; q < 8; q++) {
                float4 f = s4[q];
                v[4 * q + 0] = f.x; v[4 * q + 1] = f.y;
                v[4 * q + 2] = f.z; v[4 * q + 3] = f.w;
            }
        } else {
#pragma unroll
            for (int j = 0; j < 32; j++) {
                int i = akb + j;
                float val = 0.0f;
                if (i == 0)       val = vis[asrc];
                else if (i < 5)   val = bbox[(size_t)asrc * 4 + (i - 1)];
                else if (i < 56)  val = kpts[(size_t)asrc * 51 + (i - 5)];
                v[j] = val;
            }
        }
        uint32_t hw[16];
#pragma unroll
        for (int p = 0; p < 16; p++) hw[p] = f2h2(v[2 * p], v[2 * p + 1]);
#pragma unroll
        for (int g = 0; g < 4; g++) {
            uint32_t off = SW128((uint32_t)(arow * 128 + (akb + 8 * g) * 2));
            *reinterpret_cast<uint4*>(smem + ast + off) =
                make_uint4(hw[4 * g], hw[4 * g + 1], hw[4 * g + 2], hw[4 * g + 3]);
        }
    };

    // ---- prologue ----
    if (tid == 0) loadB(0);
    prodA(0);

    // ---- mainloop ----
    for (int c = 0; c < NCHUNK; c++) {
        const uint32_t baseA = sb + (uint32_t)(c & 1) * A_STAGE_SZ;
        const uint32_t baseB = sb + B_BASE + (uint32_t)(c & 1) * B_STAGE_SZ;

        __syncthreads();                     // A(c) visible; stage (c+1)&1 free
        if (tid == 0 && c + 1 < NCHUNK) loadB(c + 1);
        mbar_wait(sb + OFF_BAR + (uint32_t)(c & 1) * 8, (uint32_t)((c >> 1) & 1));

#pragma unroll
        for (int s = 0; s < 4; s++) {
            const uint32_t sseg = segBase + (uint32_t)s * 32;
            uint32_t bh[2][4];
#pragma unroll
            for (int ng = 0; ng < 2; ng++)
                ldsm4(bh[ng], baseB + b_row128[ng] + (sseg ^ b_xor[ng]));
#pragma unroll
            for (int mi = 0; mi < 4; mi++) {
                uint32_t ah[4];
                ldsm4(ah, baseA + a_row128[mi] + (sseg ^ a_xor[mi]));
#pragma unroll
                for (int ng = 0; ng < 2; ng++) {
                    float* d0 = acc[mi][2 * ng];
                    float* d1 = acc[mi][2 * ng + 1];
                    mma16816(d0[0], d0[1], d0[2], d0[3], ah, bh[ng][0], bh[ng][2]);
                    mma16816(d1[0], d1[1], d1[2], d1[3], ah, bh[ng][1], bh[ng][3]);
                }
            }
        }

        // produce A(c+1) at the tail; co-resident CTA hides the LDG latency
        if (c + 1 < NCHUNK) prodA(c + 1);
    }

    // ---- epilogue: bias + permuted scatter store (zeros for inactive rows) ----
    const float* biasS = reinterpret_cast<const float*>(smem + OFF_BIAS);
    const int lr = lane >> 2;
    const int lc = (lane & 3) * 2;
#pragma unroll
    for (int mi = 0; mi < 4; mi++) {
#pragma unroll
        for (int dh = 0; dh < 2; dh++) {
            int rloc = warpM * 64 + mi * 16 + lr + dh * 8;
            int gr = rowBase + rloc;
            int realrow = g_idx[gr];
            float* orow = out + (size_t)realrow * 256 + colBase;
            if (gr < na) {
#pragma unroll
                for (int ni = 0; ni < 4; ni++) {
                    int cl = warpN * 32 + ni * 8 + lc;
                    float2 w;
                    w.x = acc[mi][ni][2 * dh + 0] + biasS[cl];
                    w.y = acc[mi][ni][2 * dh + 1] + biasS[cl + 1];
                    *reinterpret_cast<float2*>(orow + cl) = w;
                }
            } else {
#pragma unroll
                for (int ni = 0; ni < 4; ni++) {
                    int cl = warpN * 32 + ni * 8 + lc;
                    *reinterpret_cast<float2*>(orow + cl) = make_float2(0.f, 0.f);
                }
            }
        }
    }
}

// ---------------- launch ----------------
extern "C" void kernel_launch(void* const* d_in, const int* in_sizes, int n_in,
                              void* d_out, int out_size) {
    const float* emb  = (const float*)d_in[0];
    const float* vis  = (const float*)d_in[1];
    const float* bbox = (const float*)d_in[2];
    const float* kpts = (const float*)d_in[3];
    const int*   mask = (const int*)d_in[4];
    const float* appW = (const float*)d_in[5];
    const float* appB = (const float*)d_in[6];
    const float* stW  = (const float*)d_in[7];
    const float* stB  = (const float*)d_in[8];

    static int configured = 0;
    if (!configured) {
        cudaFuncSetAttribute(seplin_mma, cudaFuncAttributeMaxDynamicSharedMemorySize,
                             SMEM_TOTAL);
        configured = 1;
    }

    k_prep1<<<64 + 36, 256>>>(appW, stW, mask);
    k_prep2<<<64, 256>>>(mask);

    dim3 grid(256 / BN, GRID_M);   // (2, 2048)
    seplin_mma<<<grid, NTHR, SMEM_TOTAL>>>(emb, vis, bbox, kpts,
                                           appB, stB, (float*)d_out);
    (void)in_sizes; (void)n_in; (void)out_size;
}

// round 17
// speedup vs baseline: 1.5715x; 1.1739x over previous
#include <cuda_runtime.h>
#include <cstdint>
#include <cstddef>

// ---------------- constants ----------------
static constexpr int BM = 128;                 // M rows per CTA
static constexpr int BN = 128;                 // N cols per CTA
static constexpr int NCHUNK = 9;               // K = 576 (568 + pad) in chunks of 64
static constexpr int MTOT = 262144;
static constexpr int GRID_M = MTOT / BM;       // 2048
static constexpr int NTHR = 256;

// dynamic smem: A 2 stages x 16KB, B 2 stages x 16KB, bias, barriers
static constexpr uint32_t A_STAGE_SZ = 16384;             // fp16 A image (128 x 128B)
static constexpr uint32_t B_BASE     = 32768;
static constexpr uint32_t B_STAGE_SZ = 16384;             // fp16 B image (128 x 128B)
static constexpr uint32_t OFF_BIAS   = B_BASE + 2 * B_STAGE_SZ;   // 65536
static constexpr uint32_t OFF_BAR    = OFF_BIAS + 512;            // 2 mbarriers
static constexpr uint32_t SMEM_TOTAL = OFF_BAR + 64;              // 66112

// prepacked swizzled B image (fp16): [chunk][n=0..255][k=0..63]  -> 32KB per chunk
__device__ __align__(128) uint32_t g_Bh[NCHUNK * 8192];
// prepacked swizzled A image (fp16): [rowblock][chunk][128 rows x 128B] -> 16KB tiles
__device__ __align__(128) uint32_t g_Ah[(size_t)GRID_M * NCHUNK * 4096];

// compaction state (two-sided: actives from front, inactives from back)
__device__ int g_idx[MTOT];
__device__ int g_blockcnt[64];
__device__ int g_NA;

// ---------------- helpers ----------------
__device__ __forceinline__ uint32_t smem_u32(const void* p) {
    uint32_t a;
    asm("{ .reg .u64 t; cvta.to.shared.u64 t, %1; cvt.u32.u64 %0, t; }"
        : "=r"(a) : "l"(p));
    return a;
}
__device__ __forceinline__ uint32_t f2h2(float lo, float hi) {
    uint32_t r;
    asm("cvt.rn.f16x2.f32 %0, %1, %2;" : "=r"(r) : "f"(hi), "f"(lo));
    return r;
}
#define SW128(o) ((o) ^ (((o) >> 3) & 0x70))

__device__ __forceinline__ void mbar_init(uint32_t a, uint32_t cnt) {
    asm volatile("mbarrier.init.shared.b64 [%0], %1;" :: "r"(a), "r"(cnt) : "memory");
}
__device__ __forceinline__ void mbar_expect(uint32_t a, uint32_t bytes) {
    asm volatile("mbarrier.arrive.expect_tx.shared.b64 _, [%0], %1;"
                 :: "r"(a), "r"(bytes) : "memory");
}
__device__ __forceinline__ void mbar_wait(uint32_t a, uint32_t ph) {
    asm volatile(
        "{\n\t.reg .pred P;\n"
        "WL%=:\n\t"
        "mbarrier.try_wait.parity.acquire.cta.shared::cta.b64 P, [%0], %1, 0x989680;\n\t"
        "@P bra WD%=;\n\t"
        "bra WL%=;\n"
        "WD%=:\n\t}"
        :: "r"(a), "r"(ph) : "memory");
}
__device__ __forceinline__ void bulk_g2s(uint32_t dst, const void* src,
                                         uint32_t bytes, uint32_t mbar) {
    asm volatile(
        "cp.async.bulk.shared::cta.global.mbarrier::complete_tx::bytes [%0], [%1], %2, [%3];"
        :: "r"(dst), "l"(src), "r"(bytes), "r"(mbar) : "memory");
}
__device__ __forceinline__ void ldsm4(uint32_t* r, uint32_t a) {
    asm volatile("ldmatrix.sync.aligned.m8n8.x4.shared.b16 {%0,%1,%2,%3}, [%4];"
                 : "=r"(r[0]), "=r"(r[1]), "=r"(r[2]), "=r"(r[3]) : "r"(a));
}
__device__ __forceinline__ void mma16816(float& d0, float& d1, float& d2, float& d3,
                                         const uint32_t* a, uint32_t b0, uint32_t b1) {
    asm volatile(
        "mma.sync.aligned.m16n8k16.row.col.f32.f16.f16.f32 "
        "{%0,%1,%2,%3}, {%4,%5,%6,%7}, {%8,%9}, {%0,%1,%2,%3};"
        : "+f"(d0), "+f"(d1), "+f"(d2), "+f"(d3)
        : "r"(a[0]), "r"(a[1]), "r"(a[2]), "r"(a[3]), "r"(b0), "r"(b1));
}

// ---------------- prep1: mask count (blocks 0..63) + pack W (blocks 64..99) ----------------
__device__ __forceinline__ float fetchW(int k, int n, const float* appW,
                                        const float* stW) {
    if (k <= 512) return appW[(size_t)k * 256 + n];
    if (k < 568)  return stW[(size_t)(k - 513) * 256 + n];
    return 0.0f;
}

__global__ void k_prep1(const float* __restrict__ appW,
                        const float* __restrict__ stW,
                        const int* __restrict__ mask) {
    int t = threadIdx.x;
    if (blockIdx.x < 64) {
        int b = blockIdx.x;
        const int4* m4 = reinterpret_cast<const int4*>(mask) + (size_t)b * 1024 + t * 4;
        int cnt = 0;
#pragma unroll
        for (int i = 0; i < 4; i++) {
            int4 x = m4[i];
            cnt += (x.x != 0) + (x.y != 0) + (x.z != 0) + (x.w != 0);
        }
#pragma unroll
        for (int o = 16; o > 0; o >>= 1) cnt += __shfl_down_sync(0xFFFFFFFFu, cnt, o);
        __shared__ int ws[8];
        if ((t & 31) == 0) ws[t >> 5] = cnt;
        __syncthreads();
        if (t == 0) {
            int s = 0;
#pragma unroll
            for (int i = 0; i < 8; i++) s += ws[i];
            g_blockcnt[b] = s;
        }
    } else {
        int bb    = blockIdx.x - 64;     // 0..35
        int chunk = bb >> 2;             // 0..8
        int q     = bb & 3;              // 0..3 -> kp quarter
        int n = t;
#pragma unroll
        for (int kp = q * 8; kp < q * 8 + 8; kp++) {
            int k0 = chunk * 64 + kp * 2;
            uint32_t hw = f2h2(fetchW(k0, n, appW, stW), fetchW(k0 + 1, n, appW, stW));
            uint32_t off = SW128((uint32_t)(n * 128 + kp * 4));
            g_Bh[chunk * 8192 + (off >> 2)] = hw;
        }
    }
}

// ---------------- prep2: scan block counts + two-sided scatter (64 blocks) ----------------
__global__ void k_prep2(const int* __restrict__ mask) {
    __shared__ int sc[64];
    __shared__ int s[256];
    __shared__ int boff;
    int b = blockIdx.x, t = threadIdx.x;

    if (t < 64) sc[t] = g_blockcnt[t];
    __syncthreads();
    for (int d = 1; d < 64; d <<= 1) {
        int add = (t >= d && t < 64) ? sc[t - d] : 0;
        __syncthreads();
        if (t < 64) sc[t] += add;
        __syncthreads();
    }
    if (t == 0) {
        boff = (b == 0) ? 0 : sc[b - 1];
        if (b == 0) g_NA = sc[63];
    }
    __syncthreads();

    int r0 = b * 4096 + t * 16;
    const int4* m4 = reinterpret_cast<const int4*>(mask) + (size_t)b * 1024 + t * 4;
    int m[16], cnt = 0;
#pragma unroll
    for (int i = 0; i < 4; i++) {
        int4 x = m4[i];
        m[4 * i + 0] = (x.x != 0); m[4 * i + 1] = (x.y != 0);
        m[4 * i + 2] = (x.z != 0); m[4 * i + 3] = (x.w != 0);
        cnt += m[4 * i] + m[4 * i + 1] + m[4 * i + 2] + m[4 * i + 3];
    }
    s[t] = cnt;
    __syncthreads();
    for (int d = 1; d < 256; d <<= 1) {
        int add = (t >= d) ? s[t - d] : 0;
        __syncthreads();
        s[t] += add;
        __syncthreads();
    }
    int act_excl = boff + s[t] - cnt;
#pragma unroll
    for (int i = 0; i < 16; i++) {
        int r = r0 + i;
        if (m[i]) {
            g_idx[act_excl] = r;
            act_excl++;
        } else {
            int inact_excl = r - act_excl;
            g_idx[MTOT - 1 - inact_excl] = r;
        }
    }
}

// ---------------- prep3: gather + fp16-convert + swizzle active A rows ----------------
__global__ void k_prep3(const float* __restrict__ emb,
                        const float* __restrict__ vis,
                        const float* __restrict__ bbox,
                        const float* __restrict__ kpts) {
    const int c  = blockIdx.x;        // chunk 0..8
    const int rb = blockIdx.y;        // rowblock 0..2047
    if (rb * BM >= g_NA) return;      // pure-zero rowblock: never read by main

    const int t    = threadIdx.x;
    const int arow = t >> 1;
    const int akb  = (t & 1) * 32;
    const int asrc = g_idx[rb * BM + arow];

    float v[32];
    if (c < 8) {
        const float4* s4 = reinterpret_cast<const float4*>(
            emb + (size_t)asrc * 512 + c * 64 + akb);
#pragma unroll
        for (int q = 0; q < 8; q++) {
            float4 f = s4[q];
            v[4 * q + 0] = f.x; v[4 * q + 1] = f.y;
            v[4 * q + 2] = f.z; v[4 * q + 3] = f.w;
        }
    } else {
#pragma unroll
        for (int j = 0; j < 32; j++) {
            int i = akb + j;
            float val = 0.0f;
            if (i == 0)       val = vis[asrc];
            else if (i < 5)   val = bbox[(size_t)asrc * 4 + (i - 1)];
            else if (i < 56)  val = kpts[(size_t)asrc * 51 + (i - 5)];
            v[j] = val;
        }
    }
    uint32_t hw[16];
#pragma unroll
    for (int p = 0; p < 16; p++) hw[p] = f2h2(v[2 * p], v[2 * p + 1]);

    uint32_t* base = g_Ah + ((size_t)rb * NCHUNK + c) * 4096;   // 16KB tile
#pragma unroll
    for (int g = 0; g < 4; g++) {
        uint32_t off = SW128((uint32_t)(arow * 128 + (akb + 8 * g) * 2));
        *reinterpret_cast<uint4*>(base + (off >> 2)) =
            make_uint4(hw[4 * g], hw[4 * g + 1], hw[4 * g + 2], hw[4 * g + 3]);
    }
}

// ---------------- main kernel: pure bulk-fed MMA loop ----------------
__global__ __launch_bounds__(NTHR, 2)
void seplin_mma(const float* __restrict__ appB,
                const float* __restrict__ stB,
                float* __restrict__ out) {
    const int na = g_NA;
    const int rowBase = blockIdx.y * BM;
    const int colBase = blockIdx.x * BN;
    const int tid  = threadIdx.x;

    // ---- pure-zero CTA: zero its 128x128 output block ----
    if (rowBase >= na) {
        int j   = tid >> 1;
        int seg = tid & 1;
        int realrow = g_idx[rowBase + j];
        float4* o4 = reinterpret_cast<float4*>(out + (size_t)realrow * 256 + colBase
                                               + seg * 64);
        float4 z = make_float4(0.f, 0.f, 0.f, 0.f);
#pragma unroll
        for (int i = 0; i < 16; i++) o4[i] = z;
        return;
    }

    extern __shared__ char smem[];
    const uint32_t sb = smem_u32(smem);
    const int lane = tid & 31;
    const int wid  = tid >> 5;
    const int warpM = wid >> 2;   // 0..1  (64 rows each)
    const int warpN = wid & 3;    // 0..3  (32 cols each)

    if (tid < 128)
        reinterpret_cast<float*>(smem + OFF_BIAS)[tid] =
            appB[colBase + tid] + stB[colBase + tid];
    if (tid == 0) {
        mbar_init(sb + OFF_BAR + 0, 1);
        mbar_init(sb + OFF_BAR + 8, 1);
    }
    asm volatile("fence.proxy.async.shared::cta;" ::: "memory");
    __syncthreads();

    // ldmatrix per-lane constants
    const uint32_t segBase = (uint32_t)(lane >> 4) * 16;
    uint32_t a_row128[4], a_xor[4];
#pragma unroll
    for (int mi = 0; mi < 4; mi++) {
        int r = warpM * 64 + mi * 16 + (lane & 15);
        a_row128[mi] = (uint32_t)r * 128;
        a_xor[mi]    = (uint32_t)(r & 7) << 4;
    }
    uint32_t b_row128[2], b_xor[2];
#pragma unroll
    for (int ng = 0; ng < 2; ng++) {
        int r = warpN * 32 + ng * 16 + (lane & 15);
        b_row128[ng] = (uint32_t)r * 128;
        b_xor[ng]    = (uint32_t)(r & 7) << 4;
    }

    float acc[4][4][4];
#pragma unroll
    for (int mi = 0; mi < 4; mi++)
#pragma unroll
        for (int ni = 0; ni < 4; ni++)
#pragma unroll
            for (int q = 0; q < 4; q++) acc[mi][ni][q] = 0.0f;

    const char* aSrc = reinterpret_cast<const char*>(
        g_Ah + (size_t)blockIdx.y * NCHUNK * 4096);

    auto loadAB = [&](int c) {
        const uint32_t aSt = (uint32_t)(c & 1) * A_STAGE_SZ;
        const uint32_t bSt = B_BASE + (uint32_t)(c & 1) * B_STAGE_SZ;
        const uint32_t bar = sb + OFF_BAR + (uint32_t)(c & 1) * 8;
        mbar_expect(bar, 32768);
        bulk_g2s(sb + aSt, aSrc + (size_t)c * 16384, 16384, bar);
        bulk_g2s(sb + bSt,
                 reinterpret_cast<const char*>(g_Bh) + (size_t)c * 32768
                     + (size_t)colBase * 128,
                 16384, bar);
    };

    // ---- prologue ----
    if (tid == 0) loadAB(0);

    // ---- mainloop ----
    for (int c = 0; c < NCHUNK; c++) {
        const uint32_t baseA = sb + (uint32_t)(c & 1) * A_STAGE_SZ;
        const uint32_t baseB = sb + B_BASE + (uint32_t)(c & 1) * B_STAGE_SZ;

        __syncthreads();                     // all warps done reading stage (c+1)&1
        if (tid == 0 && c + 1 < NCHUNK) loadAB(c + 1);
        mbar_wait(sb + OFF_BAR + (uint32_t)(c & 1) * 8, (uint32_t)((c >> 1) & 1));

#pragma unroll
        for (int s = 0; s < 4; s++) {
            const uint32_t sseg = segBase + (uint32_t)s * 32;
            uint32_t bh[2][4];
#pragma unroll
            for (int ng = 0; ng < 2; ng++)
                ldsm4(bh[ng], baseB + b_row128[ng] + (sseg ^ b_xor[ng]));
#pragma unroll
            for (int mi = 0; mi < 4; mi++) {
                uint32_t ah[4];
                ldsm4(ah, baseA + a_row128[mi] + (sseg ^ a_xor[mi]));
#pragma unroll
                for (int ng = 0; ng < 2; ng++) {
                    float* d0 = acc[mi][2 * ng];
                    float* d1 = acc[mi][2 * ng + 1];
                    mma16816(d0[0], d0[1], d0[2], d0[3], ah, bh[ng][0], bh[ng][2]);
                    mma16816(d1[0], d1[1], d1[2], d1[3], ah, bh[ng][1], bh[ng][3]);
                }
            }
        }
    }

    // ---- epilogue: bias + permuted scatter store (zeros for inactive rows) ----
    const float* biasS = reinterpret_cast<const float*>(smem + OFF_BIAS);
    const int lr = lane >> 2;
    const int lc = (lane & 3) * 2;
#pragma unroll
    for (int mi = 0; mi < 4; mi++) {
#pragma unroll
        for (int dh = 0; dh < 2; dh++) {
            int rloc = warpM * 64 + mi * 16 + lr + dh * 8;
            int gr = rowBase + rloc;
            int realrow = g_idx[gr];
            float* orow = out + (size_t)realrow * 256 + colBase;
            if (gr < na) {
#pragma unroll
                for (int ni = 0; ni < 4; ni++) {
                    int cl = warpN * 32 + ni * 8 + lc;
                    float2 w;
                    w.x = acc[mi][ni][2 * dh + 0] + biasS[cl];
                    w.y = acc[mi][ni][2 * dh + 1] + biasS[cl + 1];
                    *reinterpret_cast<float2*>(orow + cl) = w;
                }
            } else {
#pragma unroll
                for (int ni = 0; ni < 4; ni++) {
                    int cl = warpN * 32 + ni * 8 + lc;
                    *reinterpret_cast<float2*>(orow + cl) = make_float2(0.f, 0.f);
                }
            }
        }
    }
}

// ---------------- launch ----------------
extern "C" void kernel_launch(void* const* d_in, const int* in_sizes, int n_in,
                              void* d_out, int out_size) {
    const float* emb  = (const float*)d_in[0];
    const float* vis  = (const float*)d_in[1];
    const float* bbox = (const float*)d_in[2];
    const float* kpts = (const float*)d_in[3];
    const int*   mask = (const int*)d_in[4];
    const float* appW = (const float*)d_in[5];
    const float* appB = (const float*)d_in[6];
    const float* stW  = (const float*)d_in[7];
    const float* stB  = (const float*)d_in[8];

    static int configured = 0;
    if (!configured) {
        cudaFuncSetAttribute(seplin_mma, cudaFuncAttributeMaxDynamicSharedMemorySize,
                             SMEM_TOTAL);
        configured = 1;
    }

    k_prep1<<<64 + 36, 256>>>(appW, stW, mask);
    k_prep2<<<64, 256>>>(mask);
    {
        dim3 g3(NCHUNK, GRID_M);
        k_prep3<<<g3, 256>>>(emb, vis, bbox, kpts);
    }
    dim3 grid(256 / BN, GRID_M);   // (2, 2048)
    seplin_mma<<<grid, NTHR, SMEM_TOTAL>>>(appB, stB, (float*)d_out);
    (void)in_sizes; (void)n_in; (void)out_size;
}